// round 2
// baseline (speedup 1.0000x reference)
#include <cuda_runtime.h>
#include <math.h>

#define NN   10000
#define EIN  320000
#define ETOT 330000

// ---------------- device scratch (no allocations allowed) ----------------
__device__ float g_h[NN * 512];     // post-GEMM features
__device__ float g_o[NN * 512];     // post-GAT layer output
__device__ float g_als[NN * 4];
__device__ float g_ald[NN * 4];
__device__ float g_e[ETOT * 4];     // edge logits [edge*H + h]
__device__ int   g_rowptr[NN + 1];
__device__ int   g_cnt[NN];
__device__ int   g_perm[ETOT];

// edge_index is int32: row 0 = src (E entries), row 1 = dst (E entries).
// Edges [EIN, ETOT) are the appended self-loops (node = e - EIN).
__device__ __forceinline__ int edge_src(const int* ei, int e) {
    return (e < EIN) ? ei[e] : (e - EIN);
}
__device__ __forceinline__ int edge_dst(const int* ei, int e) {
    return (e < EIN) ? ei[EIN + e] : (e - EIN);
}

// ---------------- CSR build ----------------
__global__ void k_zero_cnt() {
    int i = blockIdx.x * blockDim.x + threadIdx.x;
    if (i < NN) g_cnt[i] = 0;
}

__global__ void k_count(const int* __restrict__ ei) {
    int e = blockIdx.x * blockDim.x + threadIdx.x;
    if (e < ETOT) atomicAdd(&g_cnt[edge_dst(ei, e)], 1);
}

// single-block scan over NN counts -> exclusive rowptr
__global__ void k_scan() {
    __shared__ int sh[1024];
    __shared__ int carry;
    int t = threadIdx.x;
    if (t == 0) { carry = 0; g_rowptr[0] = 0; }
    __syncthreads();
    for (int base = 0; base < NN; base += 1024) {
        int v = (base + t < NN) ? g_cnt[base + t] : 0;
        sh[t] = v;
        __syncthreads();
        for (int off = 1; off < 1024; off <<= 1) {
            int x = (t >= off) ? sh[t - off] : 0;
            __syncthreads();
            sh[t] += x;
            __syncthreads();
        }
        if (base + t < NN) g_rowptr[base + t + 1] = sh[t] + carry;
        __syncthreads();
        if (t == 0) carry += sh[1023];
        __syncthreads();
    }
}

__global__ void k_scatter(const int* __restrict__ ei) {
    int e = blockIdx.x * blockDim.x + threadIdx.x;
    if (e < ETOT) {
        int d = edge_dst(ei, e);
        int p = atomicAdd(&g_cnt[d], 1);
        g_perm[g_rowptr[d] + p] = e;
    }
}

// ---------------- SGEMM: C[M,N] = A[M,K] * B[K,N], 128x128x8 tiles ----------------
__global__ __launch_bounds__(256) void sgemm128(
    const float* __restrict__ A, const float* __restrict__ B,
    float* __restrict__ C, int M, int N, int K)
{
    __shared__ float As[8][128];
    __shared__ float Bs[8][128];

    const int tid = threadIdx.x;
    const int tx = tid & 15;          // 0..15  (N direction)
    const int ty = tid >> 4;          // 0..15  (M direction)
    const int bm = blockIdx.y * 128;
    const int bn = blockIdx.x * 128;

    const int arow = tid >> 1;            // 0..127
    const int acol = (tid & 1) * 4;       // 0 or 4
    const int brow = tid >> 5;            // 0..7
    const int bcol = (tid & 31) * 4;      // 0..124

    float acc[8][8];
#pragma unroll
    for (int i = 0; i < 8; i++)
#pragma unroll
        for (int j = 0; j < 8; j++) acc[i][j] = 0.f;

    for (int k0 = 0; k0 < K; k0 += 8) {
        float4 av = make_float4(0.f, 0.f, 0.f, 0.f);
        if (bm + arow < M)
            av = *(const float4*)&A[(size_t)(bm + arow) * K + k0 + acol];
        As[acol + 0][arow] = av.x;
        As[acol + 1][arow] = av.y;
        As[acol + 2][arow] = av.z;
        As[acol + 3][arow] = av.w;

        float4 bv = make_float4(0.f, 0.f, 0.f, 0.f);
        if (bn + bcol < N)
            bv = *(const float4*)&B[(size_t)(k0 + brow) * N + bn + bcol];
        *(float4*)&Bs[brow][bcol] = bv;

        __syncthreads();
#pragma unroll
        for (int k = 0; k < 8; k++) {
            float a[8], b[8];
            float4 a0 = *(const float4*)&As[k][ty * 8];
            float4 a1 = *(const float4*)&As[k][ty * 8 + 4];
            a[0]=a0.x; a[1]=a0.y; a[2]=a0.z; a[3]=a0.w;
            a[4]=a1.x; a[5]=a1.y; a[6]=a1.z; a[7]=a1.w;
            float4 b0 = *(const float4*)&Bs[k][tx * 8];
            float4 b1 = *(const float4*)&Bs[k][tx * 8 + 4];
            b[0]=b0.x; b[1]=b0.y; b[2]=b0.z; b[3]=b0.w;
            b[4]=b1.x; b[5]=b1.y; b[6]=b1.z; b[7]=b1.w;
#pragma unroll
            for (int i = 0; i < 8; i++)
#pragma unroll
                for (int j = 0; j < 8; j++)
                    acc[i][j] += a[i] * b[j];
        }
        __syncthreads();
    }

#pragma unroll
    for (int i = 0; i < 8; i++) {
        int r = bm + ty * 8 + i;
        if (r < M) {
            int c0 = bn + tx * 8;
            if (c0 + 3 < N)
                *(float4*)&C[(size_t)r * N + c0] =
                    make_float4(acc[i][0], acc[i][1], acc[i][2], acc[i][3]);
            if (c0 + 7 < N)
                *(float4*)&C[(size_t)r * N + c0 + 4] =
                    make_float4(acc[i][4], acc[i][5], acc[i][6], acc[i][7]);
        }
    }
}

// ---------------- per-node attention logits ----------------
__global__ void node_al(const float* __restrict__ feat,
                        const float* __restrict__ a_src,
                        const float* __restrict__ a_dst,
                        int Hn, int Cn)
{
    int n = blockIdx.x;
    int w = threadIdx.x >> 5;
    int lane = threadIdx.x & 31;
    if (w >= Hn) return;
    const float* row = feat + (size_t)n * Hn * Cn + w * Cn;
    float s1 = 0.f, s2 = 0.f;
    for (int c = lane; c < Cn; c += 32) {
        float v = row[c];
        s1 += v * a_src[w * Cn + c];
        s2 += v * a_dst[w * Cn + c];
    }
#pragma unroll
    for (int off = 16; off; off >>= 1) {
        s1 += __shfl_xor_sync(0xffffffffu, s1, off);
        s2 += __shfl_xor_sync(0xffffffffu, s2, off);
    }
    if (lane == 0) {
        g_als[n * Hn + w] = s1;
        g_ald[n * Hn + w] = s2;
    }
}

// ---------------- edge logits (leaky relu) ----------------
__global__ void k_edge(const int* __restrict__ ei, int Hn) {
    int idx = blockIdx.x * blockDim.x + threadIdx.x;
    if (idx >= ETOT * Hn) return;
    int e = idx / Hn;
    int hh = idx - e * Hn;
    int s = edge_src(ei, e);
    int d = edge_dst(ei, e);
    float v = g_als[s * Hn + hh] + g_ald[d * Hn + hh];
    g_e[idx] = (v > 0.f) ? v : 0.2f * v;
}

// ---------------- per-dst softmax + aggregation ----------------
template <int H, int C>
__global__ void gat_agg(const float* __restrict__ feat,
                        const int* __restrict__ ei,
                        const float* __restrict__ bias,
                        float* __restrict__ outp,
                        int apply_elu)
{
    constexpr int HCv = H * C;
    constexpr int CHUNK = 128;
    int n = blockIdx.x;
    int t = threadIdx.x;

    int start = g_rowptr[n];
    int deg = g_rowptr[n + 1] - start;

    __shared__ float m_sh[H];
    __shared__ float d_sh[H];
    __shared__ float alpha_sh[CHUNK * H];
    __shared__ int   src_sh[CHUNK];
    __shared__ int   eid_sh[CHUNK];

    int warp = t >> 5, lane = t & 31;
    if (warp < H) {
        float mx = -1e30f;
        for (int j = lane; j < deg; j += 32)
            mx = fmaxf(mx, g_e[g_perm[start + j] * H + warp]);
#pragma unroll
        for (int off = 16; off; off >>= 1)
            mx = fmaxf(mx, __shfl_xor_sync(0xffffffffu, mx, off));
        float s = 0.f;
        for (int j = lane; j < deg; j += 32)
            s += __expf(g_e[g_perm[start + j] * H + warp] - mx);
#pragma unroll
        for (int off = 16; off; off >>= 1)
            s += __shfl_xor_sync(0xffffffffu, s, off);
        if (lane == 0) { m_sh[warp] = mx; d_sh[warp] = s; }
    }
    __syncthreads();

    const int head = t / C;
    float acc = 0.f;

    for (int cs = 0; cs < deg; cs += CHUNK) {
        int cn = min(CHUNK, deg - cs);
        for (int i = t; i < cn; i += HCv) {
            int eidx = g_perm[start + cs + i];
            eid_sh[i] = eidx;
            src_sh[i] = edge_src(ei, eidx);
        }
        __syncthreads();
        for (int i = t; i < cn * H; i += HCv) {
            int j = i / H, hh = i - j * H;
            alpha_sh[i] = __expf(g_e[eid_sh[j] * H + hh] - m_sh[hh]) / d_sh[hh];
        }
        __syncthreads();
        for (int j = 0; j < cn; j++) {
            acc += alpha_sh[j * H + head] * feat[(size_t)src_sh[j] * HCv + t];
        }
        __syncthreads();
    }

    float v = acc + bias[t];
    if (apply_elu) v = (v > 0.f) ? v : (__expf(v) - 1.f);
    outp[(size_t)n * HCv + t] = v;
}

// ---------------- launch ----------------
extern "C" void kernel_launch(void* const* d_in, const int* in_sizes, int n_in,
                              void* d_out, int out_size)
{
    const float* x   = (const float*)d_in[0];
    const int*   ei  = (const int*)d_in[1];
    const float* W1  = (const float*)d_in[2];
    const float* as1 = (const float*)d_in[3];
    const float* ad1 = (const float*)d_in[4];
    const float* b1  = (const float*)d_in[5];
    const float* W2  = (const float*)d_in[6];
    const float* as2 = (const float*)d_in[7];
    const float* ad2 = (const float*)d_in[8];
    const float* b2  = (const float*)d_in[9];
    const float* W3  = (const float*)d_in[10];
    const float* as3 = (const float*)d_in[11];
    const float* ad3 = (const float*)d_in[12];
    const float* b3  = (const float*)d_in[13];
    float* out = (float*)d_out;

    float *h, *o;
    cudaGetSymbolAddress((void**)&h, g_h);
    cudaGetSymbolAddress((void**)&o, g_o);

    // --- CSR build (edge structure shared by all 3 layers) ---
    k_zero_cnt<<<(NN + 255) / 256, 256>>>();
    k_count<<<(ETOT + 255) / 256, 256>>>(ei);
    k_scan<<<1, 1024>>>();
    k_zero_cnt<<<(NN + 255) / 256, 256>>>();
    k_scatter<<<(ETOT + 255) / 256, 256>>>(ei);

    dim3 g1((512 + 127) / 128, (NN + 127) / 128);
    dim3 g3((64 + 127) / 128, (NN + 127) / 128);

    // --- layer 1: H=4, C=128 ---
    sgemm128<<<g1, 256>>>(x, W1, h, NN, 512, 256);
    node_al<<<NN, 128>>>(h, as1, ad1, 4, 128);
    k_edge<<<(ETOT * 4 + 255) / 256, 256>>>(ei, 4);
    gat_agg<4, 128><<<NN, 512>>>(h, ei, b1, o, 1);

    // --- layer 2: H=4, C=128 ---
    sgemm128<<<g1, 256>>>(o, W2, h, NN, 512, 512);
    node_al<<<NN, 128>>>(h, as2, ad2, 4, 128);
    k_edge<<<(ETOT * 4 + 255) / 256, 256>>>(ei, 4);
    gat_agg<4, 128><<<NN, 512>>>(h, ei, b2, o, 1);

    // --- layer 3: H=1, C=64 ---
    sgemm128<<<g3, 256>>>(o, W3, h, NN, 64, 512);
    node_al<<<NN, 32>>>(h, as3, ad3, 1, 64);
    k_edge<<<(ETOT + 255) / 256, 256>>>(ei, 1);
    gat_agg<1, 64><<<NN, 64>>>(h, ei, b3, out, 0);
}

// round 3
// speedup vs baseline: 1.3129x; 1.3129x over previous
#include <cuda_runtime.h>
#include <math.h>

#define NN   10000
#define EIN  320000
#define ETOT 330000

// ---------------- device scratch (no allocations allowed) ----------------
__device__ float g_h[NN * 512];     // post-GEMM features
__device__ float g_o[NN * 512];     // post-GAT layer output
__device__ float g_als[NN * 4];
__device__ float g_ald[NN * 4];
__device__ float g_e[ETOT * 4];     // edge logits [edge*H + h]
__device__ int   g_rowptr[NN + 1];
__device__ int   g_cnt[NN];
__device__ int   g_perm[ETOT];

__device__ __forceinline__ int edge_src(const int* ei, int e) {
    return (e < EIN) ? ei[e] : (e - EIN);
}
__device__ __forceinline__ int edge_dst(const int* ei, int e) {
    return (e < EIN) ? ei[EIN + e] : (e - EIN);
}

// ---------------- CSR build ----------------
__global__ void k_zero_cnt() {
    int i = blockIdx.x * blockDim.x + threadIdx.x;
    if (i < NN) g_cnt[i] = 0;
}

__global__ void k_count(const int* __restrict__ ei) {
    int e = blockIdx.x * blockDim.x + threadIdx.x;
    if (e < ETOT) atomicAdd(&g_cnt[edge_dst(ei, e)], 1);
}

__global__ void k_scan() {
    __shared__ int sh[1024];
    __shared__ int carry;
    int t = threadIdx.x;
    if (t == 0) { carry = 0; g_rowptr[0] = 0; }
    __syncthreads();
    for (int base = 0; base < NN; base += 1024) {
        int v = (base + t < NN) ? g_cnt[base + t] : 0;
        sh[t] = v;
        __syncthreads();
        for (int off = 1; off < 1024; off <<= 1) {
            int x = (t >= off) ? sh[t - off] : 0;
            __syncthreads();
            sh[t] += x;
            __syncthreads();
        }
        if (base + t < NN) g_rowptr[base + t + 1] = sh[t] + carry;
        __syncthreads();
        if (t == 0) carry += sh[1023];
        __syncthreads();
    }
}

__global__ void k_scatter(const int* __restrict__ ei) {
    int e = blockIdx.x * blockDim.x + threadIdx.x;
    if (e < ETOT) {
        int d = edge_dst(ei, e);
        int p = atomicAdd(&g_cnt[d], 1);
        g_perm[g_rowptr[d] + p] = e;
    }
}

// ---------------- TF32 tensor-core GEMM ----------------
// C[M,N] = A[M,K] * B[K,N]; 128x128 block tile, K-tile 32, 8 warps (2x4),
// warp tile 64x32, mma.m16n8k8 tf32.
__device__ __forceinline__ unsigned f2tf32(float f) {
    unsigned r;
    asm("cvt.rna.tf32.f32 %0, %1;" : "=r"(r) : "f"(f));
    return r;
}

__global__ __launch_bounds__(256) void gemm_tf32(
    const float* __restrict__ A, const float* __restrict__ B,
    float* __restrict__ C, int M, int N, int K)
{
    __shared__ float As[128][36];   // [m][k], pad 36 (float4-alignable, conflict-free frags)
    __shared__ float Bs[128][36];   // [n][k] (transposed on load)

    const int tid  = threadIdx.x;
    const int warp = tid >> 5, lane = tid & 31;
    const int warpM = warp >> 2, warpN = warp & 3;
    const int bm = blockIdx.y * 128, bn = blockIdx.x * 128;
    const int gid = lane >> 2, tig = lane & 3;   // groupID, thread-in-group

    float c[4][4][4];
#pragma unroll
    for (int mt = 0; mt < 4; mt++)
#pragma unroll
        for (int nt = 0; nt < 4; nt++)
#pragma unroll
            for (int r = 0; r < 4; r++) c[mt][nt][r] = 0.f;

    for (int k0 = 0; k0 < K; k0 += 32) {
        // load A tile 128x32
#pragma unroll
        for (int i = 0; i < 4; i++) {
            int r  = (tid >> 3) + 32 * i;
            int kc = (tid & 7) * 4;
            float4 av = make_float4(0.f, 0.f, 0.f, 0.f);
            if (bm + r < M)
                av = *(const float4*)&A[(size_t)(bm + r) * K + k0 + kc];
            *(float4*)&As[r][kc] = av;
        }
        // load B tile 32x128 -> transposed [n][k]
#pragma unroll
        for (int i = 0; i < 4; i++) {
            int kr = (tid >> 5) + 8 * i;
            int nc = (tid & 31) * 4;
            float4 bv = make_float4(0.f, 0.f, 0.f, 0.f);
            if (bn + nc < N)
                bv = *(const float4*)&B[(size_t)(k0 + kr) * N + bn + nc];
            Bs[nc + 0][kr] = bv.x;
            Bs[nc + 1][kr] = bv.y;
            Bs[nc + 2][kr] = bv.z;
            Bs[nc + 3][kr] = bv.w;
        }
        __syncthreads();

#pragma unroll
        for (int ks = 0; ks < 4; ks++) {
            const int kb = ks * 8;
            unsigned a[4][4], b[4][2];
#pragma unroll
            for (int mt = 0; mt < 4; mt++) {
                int m = warpM * 64 + mt * 16 + gid;
                a[mt][0] = f2tf32(As[m    ][kb + tig]);
                a[mt][1] = f2tf32(As[m + 8][kb + tig]);
                a[mt][2] = f2tf32(As[m    ][kb + tig + 4]);
                a[mt][3] = f2tf32(As[m + 8][kb + tig + 4]);
            }
#pragma unroll
            for (int nt = 0; nt < 4; nt++) {
                int n = warpN * 32 + nt * 8 + gid;
                b[nt][0] = f2tf32(Bs[n][kb + tig]);
                b[nt][1] = f2tf32(Bs[n][kb + tig + 4]);
            }
#pragma unroll
            for (int mt = 0; mt < 4; mt++)
#pragma unroll
                for (int nt = 0; nt < 4; nt++) {
                    asm volatile(
                        "mma.sync.aligned.m16n8k8.row.col.f32.tf32.tf32.f32 "
                        "{%0,%1,%2,%3}, {%4,%5,%6,%7}, {%8,%9}, {%0,%1,%2,%3};"
                        : "+f"(c[mt][nt][0]), "+f"(c[mt][nt][1]),
                          "+f"(c[mt][nt][2]), "+f"(c[mt][nt][3])
                        : "r"(a[mt][0]), "r"(a[mt][1]), "r"(a[mt][2]), "r"(a[mt][3]),
                          "r"(b[nt][0]), "r"(b[nt][1]));
                }
        }
        __syncthreads();
    }

    // epilogue
#pragma unroll
    for (int mt = 0; mt < 4; mt++) {
        int row0 = bm + warpM * 64 + mt * 16 + gid;
#pragma unroll
        for (int nt = 0; nt < 4; nt++) {
            int col = bn + warpN * 32 + nt * 8 + tig * 2;
            if (col < N) {
                if (row0 < M)
                    *(float2*)&C[(size_t)row0 * N + col] =
                        make_float2(c[mt][nt][0], c[mt][nt][1]);
                if (row0 + 8 < M)
                    *(float2*)&C[(size_t)(row0 + 8) * N + col] =
                        make_float2(c[mt][nt][2], c[mt][nt][3]);
            }
        }
    }
}

// ---------------- per-node attention logits ----------------
__global__ void node_al(const float* __restrict__ feat,
                        const float* __restrict__ a_src,
                        const float* __restrict__ a_dst,
                        int Hn, int Cn)
{
    int n = blockIdx.x;
    int w = threadIdx.x >> 5;
    int lane = threadIdx.x & 31;
    if (w >= Hn) return;
    const float* row = feat + (size_t)n * Hn * Cn + w * Cn;
    float s1 = 0.f, s2 = 0.f;
    for (int c = lane; c < Cn; c += 32) {
        float v = row[c];
        s1 += v * a_src[w * Cn + c];
        s2 += v * a_dst[w * Cn + c];
    }
#pragma unroll
    for (int off = 16; off; off >>= 1) {
        s1 += __shfl_xor_sync(0xffffffffu, s1, off);
        s2 += __shfl_xor_sync(0xffffffffu, s2, off);
    }
    if (lane == 0) {
        g_als[n * Hn + w] = s1;
        g_ald[n * Hn + w] = s2;
    }
}

// ---------------- edge logits (leaky relu) ----------------
__global__ void k_edge(const int* __restrict__ ei, int Hn) {
    int idx = blockIdx.x * blockDim.x + threadIdx.x;
    if (idx >= ETOT * Hn) return;
    int e = idx / Hn;
    int hh = idx - e * Hn;
    int s = edge_src(ei, e);
    int d = edge_dst(ei, e);
    float v = g_als[s * Hn + hh] + g_ald[d * Hn + hh];
    g_e[idx] = (v > 0.f) ? v : 0.2f * v;
}

// ---------------- per-dst softmax + aggregation ----------------
template <int H, int C>
__global__ void gat_agg(const float* __restrict__ feat,
                        const int* __restrict__ ei,
                        const float* __restrict__ bias,
                        float* __restrict__ outp,
                        int apply_elu)
{
    constexpr int HCv = H * C;
    constexpr int CHUNK = 128;
    int n = blockIdx.x;
    int t = threadIdx.x;

    int start = g_rowptr[n];
    int deg = g_rowptr[n + 1] - start;

    __shared__ float m_sh[H];
    __shared__ float d_sh[H];
    __shared__ float alpha_sh[CHUNK * H];
    __shared__ int   src_sh[CHUNK];
    __shared__ int   eid_sh[CHUNK];

    int warp = t >> 5, lane = t & 31;
    if (warp < H) {
        float mx = -1e30f;
        for (int j = lane; j < deg; j += 32)
            mx = fmaxf(mx, g_e[g_perm[start + j] * H + warp]);
#pragma unroll
        for (int off = 16; off; off >>= 1)
            mx = fmaxf(mx, __shfl_xor_sync(0xffffffffu, mx, off));
        float s = 0.f;
        for (int j = lane; j < deg; j += 32)
            s += __expf(g_e[g_perm[start + j] * H + warp] - mx);
#pragma unroll
        for (int off = 16; off; off >>= 1)
            s += __shfl_xor_sync(0xffffffffu, s, off);
        if (lane == 0) { m_sh[warp] = mx; d_sh[warp] = s; }
    }
    __syncthreads();

    const int head = t / C;
    float acc = 0.f;

    for (int cs = 0; cs < deg; cs += CHUNK) {
        int cn = min(CHUNK, deg - cs);
        for (int i = t; i < cn; i += HCv) {
            int eidx = g_perm[start + cs + i];
            eid_sh[i] = eidx;
            src_sh[i] = edge_src(ei, eidx);
        }
        __syncthreads();
        for (int i = t; i < cn * H; i += HCv) {
            int j = i / H, hh = i - j * H;
            alpha_sh[i] = __expf(g_e[eid_sh[j] * H + hh] - m_sh[hh]) / d_sh[hh];
        }
        __syncthreads();
        for (int j = 0; j < cn; j++) {
            acc += alpha_sh[j * H + head] * feat[(size_t)src_sh[j] * HCv + t];
        }
        __syncthreads();
    }

    float v = acc + bias[t];
    if (apply_elu) v = (v > 0.f) ? v : (__expf(v) - 1.f);
    outp[(size_t)n * HCv + t] = v;
}

// ---------------- launch ----------------
extern "C" void kernel_launch(void* const* d_in, const int* in_sizes, int n_in,
                              void* d_out, int out_size)
{
    const float* x   = (const float*)d_in[0];
    const int*   ei  = (const int*)d_in[1];
    const float* W1  = (const float*)d_in[2];
    const float* as1 = (const float*)d_in[3];
    const float* ad1 = (const float*)d_in[4];
    const float* b1  = (const float*)d_in[5];
    const float* W2  = (const float*)d_in[6];
    const float* as2 = (const float*)d_in[7];
    const float* ad2 = (const float*)d_in[8];
    const float* b2  = (const float*)d_in[9];
    const float* W3  = (const float*)d_in[10];
    const float* as3 = (const float*)d_in[11];
    const float* ad3 = (const float*)d_in[12];
    const float* b3  = (const float*)d_in[13];
    float* out = (float*)d_out;

    float *h, *o;
    cudaGetSymbolAddress((void**)&h, g_h);
    cudaGetSymbolAddress((void**)&o, g_o);

    // --- CSR build ---
    k_zero_cnt<<<(NN + 255) / 256, 256>>>();
    k_count<<<(ETOT + 255) / 256, 256>>>(ei);
    k_scan<<<1, 1024>>>();
    k_zero_cnt<<<(NN + 255) / 256, 256>>>();
    k_scatter<<<(ETOT + 255) / 256, 256>>>(ei);

    dim3 g1((512 + 127) / 128, (NN + 127) / 128);
    dim3 g3((64 + 127) / 128, (NN + 127) / 128);

    // --- layer 1: H=4, C=128 ---
    gemm_tf32<<<g1, 256>>>(x, W1, h, NN, 512, 256);
    node_al<<<NN, 128>>>(h, as1, ad1, 4, 128);
    k_edge<<<(ETOT * 4 + 255) / 256, 256>>>(ei, 4);
    gat_agg<4, 128><<<NN, 512>>>(h, ei, b1, o, 1);

    // --- layer 2: H=4, C=128 ---
    gemm_tf32<<<g1, 256>>>(o, W2, h, NN, 512, 512);
    node_al<<<NN, 128>>>(h, as2, ad2, 4, 128);
    k_edge<<<(ETOT * 4 + 255) / 256, 256>>>(ei, 4);
    gat_agg<4, 128><<<NN, 512>>>(h, ei, b2, o, 1);

    // --- layer 3: H=1, C=64 ---
    gemm_tf32<<<g3, 256>>>(o, W3, h, NN, 64, 512);
    node_al<<<NN, 32>>>(h, as3, ad3, 1, 64);
    k_edge<<<(ETOT + 255) / 256, 256>>>(ei, 1);
    gat_agg<1, 64><<<NN, 64>>>(h, ei, b3, out, 0);
}

// round 4
// speedup vs baseline: 1.3417x; 1.0220x over previous
#include <cuda_runtime.h>
#include <math.h>

#define NN   10000
#define EIN  320000
#define ETOT 330000

// ---------------- device scratch ----------------
__device__ float g_h[NN * 512];
__device__ float g_o[NN * 512];
__device__ float g_als[NN * 4];
__device__ float g_ald[NN * 4];
__device__ float g_e[ETOT * 4];
__device__ int   g_rowptr[NN + 1];
__device__ int   g_cnt[NN];
__device__ int   g_perm[ETOT];

__device__ __forceinline__ int edge_src(const int* ei, int e) {
    return (e < EIN) ? ei[e] : (e - EIN);
}
__device__ __forceinline__ int edge_dst(const int* ei, int e) {
    return (e < EIN) ? ei[EIN + e] : (e - EIN);
}

// ---------------- CSR build ----------------
__global__ void k_zero_cnt() {
    int i = blockIdx.x * blockDim.x + threadIdx.x;
    if (i < NN) g_cnt[i] = 0;
}

__global__ void k_count(const int* __restrict__ ei) {
    int e = blockIdx.x * blockDim.x + threadIdx.x;
    if (e < ETOT) atomicAdd(&g_cnt[edge_dst(ei, e)], 1);
}

// single-block scan, shfl-based (2 barriers per 1024-chunk)
__global__ void k_scan() {
    __shared__ int warp_sums[32];
    __shared__ int carry_sh;
    int t = threadIdx.x, lane = t & 31, w = t >> 5;
    if (t == 0) { carry_sh = 0; g_rowptr[0] = 0; }
    __syncthreads();
    for (int base = 0; base < NN; base += 1024) {
        int v = (base + t < NN) ? g_cnt[base + t] : 0;
        int s = v;
#pragma unroll
        for (int off = 1; off < 32; off <<= 1) {
            int x = __shfl_up_sync(0xffffffffu, s, off);
            if (lane >= off) s += x;
        }
        if (lane == 31) warp_sums[w] = s;
        __syncthreads();
        if (w == 0) {
            int ws = warp_sums[lane];
#pragma unroll
            for (int off = 1; off < 32; off <<= 1) {
                int x = __shfl_up_sync(0xffffffffu, ws, off);
                if (lane >= off) ws += x;
            }
            warp_sums[lane] = ws;
        }
        __syncthreads();
        int incl = s + ((w > 0) ? warp_sums[w - 1] : 0) + carry_sh;
        if (base + t < NN) g_rowptr[base + t + 1] = incl;
        __syncthreads();
        if (t == 1023) carry_sh = incl;
        __syncthreads();
    }
}

__global__ void k_scatter(const int* __restrict__ ei) {
    int e = blockIdx.x * blockDim.x + threadIdx.x;
    if (e < ETOT) {
        int d = edge_dst(ei, e);
        int p = atomicAdd(&g_cnt[d], 1);
        g_perm[g_rowptr[d] + p] = e;
    }
}

// ---------------- TF32 tensor-core GEMM, pipelined ----------------
__device__ __forceinline__ unsigned f2tf32(float f) {
    unsigned r;
    asm("cvt.rna.tf32.f32 %0, %1;" : "=r"(r) : "f"(f));
    return r;
}

// 128x128 block tile, K-tile 32, 8 warps (2x4), warp tile 64x32.
// smem holds tf32-converted operands; next K-tile prefetched into registers.
__global__ __launch_bounds__(256) void gemm_tf32(
    const float* __restrict__ A, const float* __restrict__ B,
    float* __restrict__ C, int M, int N, int K)
{
    __shared__ unsigned As[128][36];   // [m][k]
    __shared__ unsigned Bs[128][36];   // [n][k]

    const int tid  = threadIdx.x;
    const int warp = tid >> 5, lane = tid & 31;
    const int warpM = warp >> 2, warpN = warp & 3;
    const int bm = blockIdx.y * 128, bn = blockIdx.x * 128;
    const int gid = lane >> 2, tig = lane & 3;

    // A tile: 128x32, 4 float4 per thread
    const int arow = tid >> 3;          // 0..31 (+32*i)
    const int acol = (tid & 7) * 4;     // 0..28
    // B tile: 32x128, 4 float4 per thread
    const int brow = tid >> 5;          // 0..7 (+8*i)
    const int bcol = (tid & 31) * 4;    // 0..124

    float c[4][4][4];
#pragma unroll
    for (int mt = 0; mt < 4; mt++)
#pragma unroll
        for (int nt = 0; nt < 4; nt++)
#pragma unroll
            for (int r = 0; r < 4; r++) c[mt][nt][r] = 0.f;

    const int ntiles = K >> 5;
    float4 pa[4], pb[4];

    // load tile 0
#pragma unroll
    for (int i = 0; i < 4; i++) {
        int r = arow + 32 * i;
        pa[i] = make_float4(0.f, 0.f, 0.f, 0.f);
        if (bm + r < M) pa[i] = *(const float4*)&A[(size_t)(bm + r) * K + acol];
        pb[i] = make_float4(0.f, 0.f, 0.f, 0.f);
        if (bn + bcol < N) pb[i] = *(const float4*)&B[(size_t)(brow + 8 * i) * N + bn + bcol];
    }
    // store tile 0 (tf32)
#pragma unroll
    for (int i = 0; i < 4; i++) {
        int r = arow + 32 * i;
        As[r][acol + 0] = f2tf32(pa[i].x);
        As[r][acol + 1] = f2tf32(pa[i].y);
        As[r][acol + 2] = f2tf32(pa[i].z);
        As[r][acol + 3] = f2tf32(pa[i].w);
        int kr = brow + 8 * i;
        Bs[bcol + 0][kr] = f2tf32(pb[i].x);
        Bs[bcol + 1][kr] = f2tf32(pb[i].y);
        Bs[bcol + 2][kr] = f2tf32(pb[i].z);
        Bs[bcol + 3][kr] = f2tf32(pb[i].w);
    }
    __syncthreads();

    for (int kt = 0; kt < ntiles; kt++) {
        const bool more = (kt + 1 < ntiles);
        if (more) {
            const int k0 = (kt + 1) << 5;
#pragma unroll
            for (int i = 0; i < 4; i++) {
                int r = arow + 32 * i;
                pa[i] = make_float4(0.f, 0.f, 0.f, 0.f);
                if (bm + r < M) pa[i] = *(const float4*)&A[(size_t)(bm + r) * K + k0 + acol];
                pb[i] = make_float4(0.f, 0.f, 0.f, 0.f);
                if (bn + bcol < N) pb[i] = *(const float4*)&B[(size_t)(k0 + brow + 8 * i) * N + bn + bcol];
            }
        }

#pragma unroll
        for (int ks = 0; ks < 4; ks++) {
            const int kb = ks * 8;
            unsigned a[4][4], b[4][2];
#pragma unroll
            for (int mt = 0; mt < 4; mt++) {
                int m = warpM * 64 + mt * 16 + gid;
                a[mt][0] = As[m    ][kb + tig];
                a[mt][1] = As[m + 8][kb + tig];
                a[mt][2] = As[m    ][kb + tig + 4];
                a[mt][3] = As[m + 8][kb + tig + 4];
            }
#pragma unroll
            for (int nt = 0; nt < 4; nt++) {
                int n = warpN * 32 + nt * 8 + gid;
                b[nt][0] = Bs[n][kb + tig];
                b[nt][1] = Bs[n][kb + tig + 4];
            }
#pragma unroll
            for (int mt = 0; mt < 4; mt++)
#pragma unroll
                for (int nt = 0; nt < 4; nt++) {
                    asm volatile(
                        "mma.sync.aligned.m16n8k8.row.col.f32.tf32.tf32.f32 "
                        "{%0,%1,%2,%3}, {%4,%5,%6,%7}, {%8,%9}, {%0,%1,%2,%3};"
                        : "+f"(c[mt][nt][0]), "+f"(c[mt][nt][1]),
                          "+f"(c[mt][nt][2]), "+f"(c[mt][nt][3])
                        : "r"(a[mt][0]), "r"(a[mt][1]), "r"(a[mt][2]), "r"(a[mt][3]),
                          "r"(b[nt][0]), "r"(b[nt][1]));
                }
        }
        __syncthreads();
        if (more) {
#pragma unroll
            for (int i = 0; i < 4; i++) {
                int r = arow + 32 * i;
                As[r][acol + 0] = f2tf32(pa[i].x);
                As[r][acol + 1] = f2tf32(pa[i].y);
                As[r][acol + 2] = f2tf32(pa[i].z);
                As[r][acol + 3] = f2tf32(pa[i].w);
                int kr = brow + 8 * i;
                Bs[bcol + 0][kr] = f2tf32(pb[i].x);
                Bs[bcol + 1][kr] = f2tf32(pb[i].y);
                Bs[bcol + 2][kr] = f2tf32(pb[i].z);
                Bs[bcol + 3][kr] = f2tf32(pb[i].w);
            }
            __syncthreads();
        }
    }

    // epilogue
#pragma unroll
    for (int mt = 0; mt < 4; mt++) {
        int row0 = bm + warpM * 64 + mt * 16 + gid;
#pragma unroll
        for (int nt = 0; nt < 4; nt++) {
            int col = bn + warpN * 32 + nt * 8 + tig * 2;
            if (col < N) {
                if (row0 < M)
                    *(float2*)&C[(size_t)row0 * N + col] =
                        make_float2(c[mt][nt][0], c[mt][nt][1]);
                if (row0 + 8 < M)
                    *(float2*)&C[(size_t)(row0 + 8) * N + col] =
                        make_float2(c[mt][nt][2], c[mt][nt][3]);
            }
        }
    }
}

// ---------------- per-node attention logits ----------------
__global__ void node_al(const float* __restrict__ feat,
                        const float* __restrict__ a_src,
                        const float* __restrict__ a_dst,
                        int Hn, int Cn)
{
    int n = blockIdx.x;
    int w = threadIdx.x >> 5;
    int lane = threadIdx.x & 31;
    if (w >= Hn) return;
    const float* row = feat + (size_t)n * Hn * Cn + w * Cn;
    float s1 = 0.f, s2 = 0.f;
    for (int c = lane; c < Cn; c += 32) {
        float v = row[c];
        s1 += v * a_src[w * Cn + c];
        s2 += v * a_dst[w * Cn + c];
    }
#pragma unroll
    for (int off = 16; off; off >>= 1) {
        s1 += __shfl_xor_sync(0xffffffffu, s1, off);
        s2 += __shfl_xor_sync(0xffffffffu, s2, off);
    }
    if (lane == 0) {
        g_als[n * Hn + w] = s1;
        g_ald[n * Hn + w] = s2;
    }
}

// ---------------- edge logits ----------------
__global__ void k_edge(const int* __restrict__ ei, int Hn) {
    int idx = blockIdx.x * blockDim.x + threadIdx.x;
    if (idx >= ETOT * Hn) return;
    int e = idx / Hn;
    int hh = idx - e * Hn;
    int s = edge_src(ei, e);
    int d = edge_dst(ei, e);
    float v = g_als[s * Hn + hh] + g_ald[d * Hn + hh];
    g_e[idx] = (v > 0.f) ? v : 0.2f * v;
}

// ---------------- per-dst softmax + aggregation ----------------
template <int H, int C>
__global__ void gat_agg(const float* __restrict__ feat,
                        const int* __restrict__ ei,
                        const float* __restrict__ bias,
                        float* __restrict__ outp,
                        int apply_elu)
{
    constexpr int HCv = H * C;
    constexpr int CHUNK = 128;
    int n = blockIdx.x;
    int t = threadIdx.x;

    int start = g_rowptr[n];
    int deg = g_rowptr[n + 1] - start;

    __shared__ float m_sh[H];
    __shared__ float d_sh[H];
    __shared__ float alpha_sh[CHUNK * H];
    __shared__ int   src_sh[CHUNK];
    __shared__ int   eid_sh[CHUNK];

    int warp = t >> 5, lane = t & 31;
    if (warp < H) {
        float mx = -1e30f;
        for (int j = lane; j < deg; j += 32)
            mx = fmaxf(mx, g_e[g_perm[start + j] * H + warp]);
#pragma unroll
        for (int off = 16; off; off >>= 1)
            mx = fmaxf(mx, __shfl_xor_sync(0xffffffffu, mx, off));
        float s = 0.f;
        for (int j = lane; j < deg; j += 32)
            s += __expf(g_e[g_perm[start + j] * H + warp] - mx);
#pragma unroll
        for (int off = 16; off; off >>= 1)
            s += __shfl_xor_sync(0xffffffffu, s, off);
        if (lane == 0) { m_sh[warp] = mx; d_sh[warp] = s; }
    }
    __syncthreads();

    const int head = t / C;
    float acc = 0.f;

    for (int cs = 0; cs < deg; cs += CHUNK) {
        int cn = min(CHUNK, deg - cs);
        for (int i = t; i < cn; i += HCv) {
            int eidx = g_perm[start + cs + i];
            eid_sh[i] = eidx;
            src_sh[i] = edge_src(ei, eidx);
        }
        __syncthreads();
        for (int i = t; i < cn * H; i += HCv) {
            int j = i / H, hh = i - j * H;
            alpha_sh[i] = __expf(g_e[eid_sh[j] * H + hh] - m_sh[hh]) / d_sh[hh];
        }
        __syncthreads();
#pragma unroll 4
        for (int j = 0; j < cn; j++) {
            acc += alpha_sh[j * H + head] * feat[(size_t)src_sh[j] * HCv + t];
        }
        __syncthreads();
    }

    float v = acc + bias[t];
    if (apply_elu) v = (v > 0.f) ? v : (__expf(v) - 1.f);
    outp[(size_t)n * HCv + t] = v;
}

// ---------------- launch ----------------
extern "C" void kernel_launch(void* const* d_in, const int* in_sizes, int n_in,
                              void* d_out, int out_size)
{
    const float* x   = (const float*)d_in[0];
    const int*   ei  = (const int*)d_in[1];
    const float* W1  = (const float*)d_in[2];
    const float* as1 = (const float*)d_in[3];
    const float* ad1 = (const float*)d_in[4];
    const float* b1  = (const float*)d_in[5];
    const float* W2  = (const float*)d_in[6];
    const float* as2 = (const float*)d_in[7];
    const float* ad2 = (const float*)d_in[8];
    const float* b2  = (const float*)d_in[9];
    const float* W3  = (const float*)d_in[10];
    const float* as3 = (const float*)d_in[11];
    const float* ad3 = (const float*)d_in[12];
    const float* b3  = (const float*)d_in[13];
    float* out = (float*)d_out;

    float *h, *o;
    cudaGetSymbolAddress((void**)&h, g_h);
    cudaGetSymbolAddress((void**)&o, g_o);

    // --- CSR build ---
    k_zero_cnt<<<(NN + 255) / 256, 256>>>();
    k_count<<<(ETOT + 255) / 256, 256>>>(ei);
    k_scan<<<1, 1024>>>();
    k_zero_cnt<<<(NN + 255) / 256, 256>>>();
    k_scatter<<<(ETOT + 255) / 256, 256>>>(ei);

    dim3 g1((512 + 127) / 128, (NN + 127) / 128);
    dim3 g3((64 + 127) / 128, (NN + 127) / 128);

    // --- layer 1 ---
    gemm_tf32<<<g1, 256>>>(x, W1, h, NN, 512, 256);
    node_al<<<NN, 128>>>(h, as1, ad1, 4, 128);
    k_edge<<<(ETOT * 4 + 255) / 256, 256>>>(ei, 4);
    gat_agg<4, 128><<<NN, 512>>>(h, ei, b1, o, 1);

    // --- layer 2 ---
    gemm_tf32<<<g1, 256>>>(o, W2, h, NN, 512, 512);
    node_al<<<NN, 128>>>(h, as2, ad2, 4, 128);
    k_edge<<<(ETOT * 4 + 255) / 256, 256>>>(ei, 4);
    gat_agg<4, 128><<<NN, 512>>>(h, ei, b2, o, 1);

    // --- layer 3 ---
    gemm_tf32<<<g3, 256>>>(o, W3, h, NN, 64, 512);
    node_al<<<NN, 32>>>(h, as3, ad3, 1, 64);
    k_edge<<<(ETOT + 255) / 256, 256>>>(ei, 1);
    gat_agg<1, 64><<<NN, 64>>>(h, ei, b3, out, 0);
}

// round 5
// speedup vs baseline: 1.4868x; 1.1081x over previous
#include <cuda_runtime.h>
#include <cuda_fp16.h>
#include <math.h>

#define NN   10000
#define EIN  320000
#define ETOT 330000

// ---------------- device scratch ----------------
__device__ float g_h[NN * 512];
__device__ float g_o[NN * 512];
__device__ float g_als[NN * 4];
__device__ float g_ald[NN * 4];
__device__ float g_e[ETOT * 4];
__device__ int   g_rowptr[NN + 1];
__device__ int   g_cnt[NN];
__device__ int   g_perm[ETOT];

__device__ __forceinline__ int edge_src(const int* ei, int e) {
    return (e < EIN) ? ei[e] : (e - EIN);
}
__device__ __forceinline__ int edge_dst(const int* ei, int e) {
    return (e < EIN) ? ei[EIN + e] : (e - EIN);
}

// ---------------- CSR build ----------------
__global__ void k_zero_cnt() {
    int i = blockIdx.x * blockDim.x + threadIdx.x;
    if (i < NN) g_cnt[i] = 0;
}

__global__ void k_count(const int* __restrict__ ei) {
    int e = blockIdx.x * blockDim.x + threadIdx.x;
    if (e < ETOT) atomicAdd(&g_cnt[edge_dst(ei, e)], 1);
}

__global__ void k_scan() {
    __shared__ int warp_sums[32];
    __shared__ int carry_sh;
    int t = threadIdx.x, lane = t & 31, w = t >> 5;
    if (t == 0) { carry_sh = 0; g_rowptr[0] = 0; }
    __syncthreads();
    for (int base = 0; base < NN; base += 1024) {
        int v = (base + t < NN) ? g_cnt[base + t] : 0;
        int s = v;
#pragma unroll
        for (int off = 1; off < 32; off <<= 1) {
            int x = __shfl_up_sync(0xffffffffu, s, off);
            if (lane >= off) s += x;
        }
        if (lane == 31) warp_sums[w] = s;
        __syncthreads();
        if (w == 0) {
            int ws = warp_sums[lane];
#pragma unroll
            for (int off = 1; off < 32; off <<= 1) {
                int x = __shfl_up_sync(0xffffffffu, ws, off);
                if (lane >= off) ws += x;
            }
            warp_sums[lane] = ws;
        }
        __syncthreads();
        int incl = s + ((w > 0) ? warp_sums[w - 1] : 0) + carry_sh;
        if (base + t < NN) g_rowptr[base + t + 1] = incl;
        __syncthreads();
        if (t == 1023) carry_sh = incl;
        __syncthreads();
    }
}

__global__ void k_scatter(const int* __restrict__ ei) {
    int e = blockIdx.x * blockDim.x + threadIdx.x;
    if (e < ETOT) {
        int d = edge_dst(ei, e);
        int p = atomicAdd(&g_cnt[d], 1);
        g_perm[g_rowptr[d] + p] = e;
    }
}

// ---------------- FP16 tensor-core GEMM (ldmatrix + m16n8k16) ----------------
// C[M,N] = A[M,K]*B[K,N]; 128x128 block, K-tile 32, 8 warps (2x4), warp 64x32.
__global__ __launch_bounds__(256) void gemm_f16(
    const float* __restrict__ A, const float* __restrict__ B,
    float* __restrict__ C, int M, int N, int K)
{
    __shared__ __half As[128][40];   // [m][k], pitch 40 halves (80B) -> ldsm conflict-free
    __shared__ __half Bs[128][40];   // [n][k]

    const int tid  = threadIdx.x;
    const int warp = tid >> 5, lane = tid & 31;
    const int warpM = warp >> 2, warpN = warp & 3;
    const int bm = blockIdx.y * 128, bn = blockIdx.x * 128;
    const int gid = lane >> 2, tig = lane & 3;

    const int arow = tid >> 3;          // 0..31 (+32*i)
    const int acol = (tid & 7) * 4;     // 0..28
    const int brow = tid >> 5;          // 0..7 (+8*i)
    const int bcol = (tid & 31) * 4;    // 0..124

    const unsigned sAs = (unsigned)__cvta_generic_to_shared(&As[0][0]);
    const unsigned sBs = (unsigned)__cvta_generic_to_shared(&Bs[0][0]);

    float c[4][4][4];
#pragma unroll
    for (int mt = 0; mt < 4; mt++)
#pragma unroll
        for (int nt = 0; nt < 4; nt++)
#pragma unroll
            for (int r = 0; r < 4; r++) c[mt][nt][r] = 0.f;

    const int ntiles = K >> 5;
    float4 pa[4], pb[4];

#pragma unroll
    for (int i = 0; i < 4; i++) {
        int r = arow + 32 * i;
        pa[i] = make_float4(0.f, 0.f, 0.f, 0.f);
        if (bm + r < M) pa[i] = *(const float4*)&A[(size_t)(bm + r) * K + acol];
        pb[i] = make_float4(0.f, 0.f, 0.f, 0.f);
        if (bn + bcol < N) pb[i] = *(const float4*)&B[(size_t)(brow + 8 * i) * N + bn + bcol];
    }
#pragma unroll
    for (int i = 0; i < 4; i++) {
        int r = arow + 32 * i;
        *(__half2*)&As[r][acol]     = __floats2half2_rn(pa[i].x, pa[i].y);
        *(__half2*)&As[r][acol + 2] = __floats2half2_rn(pa[i].z, pa[i].w);
        int kr = brow + 8 * i;
        Bs[bcol + 0][kr] = __float2half_rn(pb[i].x);
        Bs[bcol + 1][kr] = __float2half_rn(pb[i].y);
        Bs[bcol + 2][kr] = __float2half_rn(pb[i].z);
        Bs[bcol + 3][kr] = __float2half_rn(pb[i].w);
    }
    __syncthreads();

    for (int kt = 0; kt < ntiles; kt++) {
        const bool more = (kt + 1 < ntiles);
        if (more) {
            const int k0 = (kt + 1) << 5;
#pragma unroll
            for (int i = 0; i < 4; i++) {
                int r = arow + 32 * i;
                pa[i] = make_float4(0.f, 0.f, 0.f, 0.f);
                if (bm + r < M) pa[i] = *(const float4*)&A[(size_t)(bm + r) * K + k0 + acol];
                pb[i] = make_float4(0.f, 0.f, 0.f, 0.f);
                if (bn + bcol < N) pb[i] = *(const float4*)&B[(size_t)(k0 + brow + 8 * i) * N + bn + bcol];
            }
        }

#pragma unroll
        for (int ks = 0; ks < 2; ks++) {
            const int kb = ks * 16;
            unsigned a[4][4], b[4][2];
#pragma unroll
            for (int mt = 0; mt < 4; mt++) {
                int m  = warpM * 64 + mt * 16 + (lane & 15);
                int kc = kb + 8 * (lane >> 4);
                unsigned addr = sAs + (unsigned)(m * 40 + kc) * 2u;
                asm volatile(
                    "ldmatrix.sync.aligned.m8n8.x4.shared.b16 {%0,%1,%2,%3}, [%4];"
                    : "=r"(a[mt][0]), "=r"(a[mt][1]), "=r"(a[mt][2]), "=r"(a[mt][3])
                    : "r"(addr));
            }
#pragma unroll
            for (int np = 0; np < 2; np++) {
                int n  = warpN * 32 + np * 16 + (lane & 7) + ((lane >> 4) & 1) * 8;
                int kc = kb + ((lane >> 3) & 1) * 8;
                unsigned addr = sBs + (unsigned)(n * 40 + kc) * 2u;
                unsigned r0, r1, r2, r3;
                asm volatile(
                    "ldmatrix.sync.aligned.m8n8.x4.shared.b16 {%0,%1,%2,%3}, [%4];"
                    : "=r"(r0), "=r"(r1), "=r"(r2), "=r"(r3)
                    : "r"(addr));
                b[np * 2][0]     = r0;
                b[np * 2][1]     = r1;
                b[np * 2 + 1][0] = r2;
                b[np * 2 + 1][1] = r3;
            }
#pragma unroll
            for (int mt = 0; mt < 4; mt++)
#pragma unroll
                for (int nt = 0; nt < 4; nt++) {
                    asm volatile(
                        "mma.sync.aligned.m16n8k16.row.col.f32.f16.f16.f32 "
                        "{%0,%1,%2,%3}, {%4,%5,%6,%7}, {%8,%9}, {%0,%1,%2,%3};"
                        : "+f"(c[mt][nt][0]), "+f"(c[mt][nt][1]),
                          "+f"(c[mt][nt][2]), "+f"(c[mt][nt][3])
                        : "r"(a[mt][0]), "r"(a[mt][1]), "r"(a[mt][2]), "r"(a[mt][3]),
                          "r"(b[nt][0]), "r"(b[nt][1]));
                }
        }
        __syncthreads();
        if (more) {
#pragma unroll
            for (int i = 0; i < 4; i++) {
                int r = arow + 32 * i;
                *(__half2*)&As[r][acol]     = __floats2half2_rn(pa[i].x, pa[i].y);
                *(__half2*)&As[r][acol + 2] = __floats2half2_rn(pa[i].z, pa[i].w);
                int kr = brow + 8 * i;
                Bs[bcol + 0][kr] = __float2half_rn(pb[i].x);
                Bs[bcol + 1][kr] = __float2half_rn(pb[i].y);
                Bs[bcol + 2][kr] = __float2half_rn(pb[i].z);
                Bs[bcol + 3][kr] = __float2half_rn(pb[i].w);
            }
            __syncthreads();
        }
    }

#pragma unroll
    for (int mt = 0; mt < 4; mt++) {
        int row0 = bm + warpM * 64 + mt * 16 + gid;
#pragma unroll
        for (int nt = 0; nt < 4; nt++) {
            int col = bn + warpN * 32 + nt * 8 + tig * 2;
            if (col < N) {
                if (row0 < M)
                    *(float2*)&C[(size_t)row0 * N + col] =
                        make_float2(c[mt][nt][0], c[mt][nt][1]);
                if (row0 + 8 < M)
                    *(float2*)&C[(size_t)(row0 + 8) * N + col] =
                        make_float2(c[mt][nt][2], c[mt][nt][3]);
            }
        }
    }
}

// ---------------- per-node attention logits ----------------
__global__ void node_al(const float* __restrict__ feat,
                        const float* __restrict__ a_src,
                        const float* __restrict__ a_dst,
                        int Hn, int Cn)
{
    int n = blockIdx.x;
    int w = threadIdx.x >> 5;
    int lane = threadIdx.x & 31;
    if (w >= Hn) return;
    const float* row = feat + (size_t)n * Hn * Cn + w * Cn;
    float s1 = 0.f, s2 = 0.f;
    for (int c = lane; c < Cn; c += 32) {
        float v = row[c];
        s1 += v * a_src[w * Cn + c];
        s2 += v * a_dst[w * Cn + c];
    }
#pragma unroll
    for (int off = 16; off; off >>= 1) {
        s1 += __shfl_xor_sync(0xffffffffu, s1, off);
        s2 += __shfl_xor_sync(0xffffffffu, s2, off);
    }
    if (lane == 0) {
        g_als[n * Hn + w] = s1;
        g_ald[n * Hn + w] = s2;
    }
}

// ---------------- edge logits ----------------
__global__ void k_edge(const int* __restrict__ ei, int Hn) {
    int idx = blockIdx.x * blockDim.x + threadIdx.x;
    if (idx >= ETOT * Hn) return;
    int e = idx / Hn;
    int hh = idx - e * Hn;
    int s = edge_src(ei, e);
    int d = edge_dst(ei, e);
    float v = g_als[s * Hn + hh] + g_ald[d * Hn + hh];
    g_e[idx] = (v > 0.f) ? v : 0.2f * v;
}

// ---------------- per-dst softmax + aggregation ----------------
template <int H, int C>
__global__ void gat_agg(const float* __restrict__ feat,
                        const int* __restrict__ ei,
                        const float* __restrict__ bias,
                        float* __restrict__ outp,
                        int apply_elu)
{
    constexpr int HCv = H * C;
    constexpr int CHUNK = 128;
    int n = blockIdx.x;
    int t = threadIdx.x;

    int start = g_rowptr[n];
    int deg = g_rowptr[n + 1] - start;

    __shared__ float m_sh[H];
    __shared__ float d_sh[H];
    __shared__ float alpha_sh[CHUNK * H];
    __shared__ int   src_sh[CHUNK];
    __shared__ int   eid_sh[CHUNK];

    int warp = t >> 5, lane = t & 31;
    if (warp < H) {
        float mx = -1e30f;
        for (int j = lane; j < deg; j += 32)
            mx = fmaxf(mx, g_e[g_perm[start + j] * H + warp]);
#pragma unroll
        for (int off = 16; off; off >>= 1)
            mx = fmaxf(mx, __shfl_xor_sync(0xffffffffu, mx, off));
        float s = 0.f;
        for (int j = lane; j < deg; j += 32)
            s += __expf(g_e[g_perm[start + j] * H + warp] - mx);
#pragma unroll
        for (int off = 16; off; off >>= 1)
            s += __shfl_xor_sync(0xffffffffu, s, off);
        if (lane == 0) { m_sh[warp] = mx; d_sh[warp] = s; }
    }
    __syncthreads();

    const int head = t / C;
    float acc = 0.f;

    for (int cs = 0; cs < deg; cs += CHUNK) {
        int cn = min(CHUNK, deg - cs);
        for (int i = t; i < cn; i += HCv) {
            int eidx = g_perm[start + cs + i];
            eid_sh[i] = eidx;
            src_sh[i] = edge_src(ei, eidx);
        }
        __syncthreads();
        for (int i = t; i < cn * H; i += HCv) {
            int j = i / H, hh = i - j * H;
            alpha_sh[i] = __expf(g_e[eid_sh[j] * H + hh] - m_sh[hh]) / d_sh[hh];
        }
        __syncthreads();
#pragma unroll 4
        for (int j = 0; j < cn; j++) {
            acc += alpha_sh[j * H + head] * feat[(size_t)src_sh[j] * HCv + t];
        }
        __syncthreads();
    }

    float v = acc + bias[t];
    if (apply_elu) v = (v > 0.f) ? v : (__expf(v) - 1.f);
    outp[(size_t)n * HCv + t] = v;
}

// ---------------- launch ----------------
extern "C" void kernel_launch(void* const* d_in, const int* in_sizes, int n_in,
                              void* d_out, int out_size)
{
    const float* x   = (const float*)d_in[0];
    const int*   ei  = (const int*)d_in[1];
    const float* W1  = (const float*)d_in[2];
    const float* as1 = (const float*)d_in[3];
    const float* ad1 = (const float*)d_in[4];
    const float* b1  = (const float*)d_in[5];
    const float* W2  = (const float*)d_in[6];
    const float* as2 = (const float*)d_in[7];
    const float* ad2 = (const float*)d_in[8];
    const float* b2  = (const float*)d_in[9];
    const float* W3  = (const float*)d_in[10];
    const float* as3 = (const float*)d_in[11];
    const float* ad3 = (const float*)d_in[12];
    const float* b3  = (const float*)d_in[13];
    float* out = (float*)d_out;

    float *h, *o;
    cudaGetSymbolAddress((void**)&h, g_h);
    cudaGetSymbolAddress((void**)&o, g_o);

    // --- CSR build ---
    k_zero_cnt<<<(NN + 255) / 256, 256>>>();
    k_count<<<(ETOT + 255) / 256, 256>>>(ei);
    k_scan<<<1, 1024>>>();
    k_zero_cnt<<<(NN + 255) / 256, 256>>>();
    k_scatter<<<(ETOT + 255) / 256, 256>>>(ei);

    dim3 g1((512 + 127) / 128, (NN + 127) / 128);
    dim3 g3((64 + 127) / 128, (NN + 127) / 128);

    // --- layer 1 ---
    gemm_f16<<<g1, 256>>>(x, W1, h, NN, 512, 256);
    node_al<<<NN, 128>>>(h, as1, ad1, 4, 128);
    k_edge<<<(ETOT * 4 + 255) / 256, 256>>>(ei, 4);
    gat_agg<4, 128><<<NN, 512>>>(h, ei, b1, o, 1);

    // --- layer 2 ---
    gemm_f16<<<g1, 256>>>(o, W2, h, NN, 512, 512);
    node_al<<<NN, 128>>>(h, as2, ad2, 4, 128);
    k_edge<<<(ETOT * 4 + 255) / 256, 256>>>(ei, 4);
    gat_agg<4, 128><<<NN, 512>>>(h, ei, b2, o, 1);

    // --- layer 3 ---
    gemm_f16<<<g3, 256>>>(o, W3, h, NN, 64, 512);
    node_al<<<NN, 32>>>(h, as3, ad3, 1, 64);
    k_edge<<<(ETOT + 255) / 256, 256>>>(ei, 1);
    gat_agg<1, 64><<<NN, 64>>>(h, ei, b3, out, 0);
}

// round 6
// speedup vs baseline: 1.8690x; 1.2571x over previous
#include <cuda_runtime.h>
#include <cuda_fp16.h>
#include <math.h>

#define NN   10000
#define EIN  320000
#define ETOT 330000

// ---------------- device scratch ----------------
__device__ __half g_x16[NN * 256];
__device__ __half g_w1[256 * 512];
__device__ __half g_w2[512 * 512];
__device__ __half g_w3[512 * 64 + 256];   // pad for OOB-column reads in 128-wide tile
__device__ __half g_h16[NN * 512];        // post-GEMM features (fp16)
__device__ __half g_o16[NN * 512];        // post-agg features (fp16)
__device__ float  g_als[NN * 4];
__device__ float  g_ald[NN * 4];
__device__ float  g_e[ETOT * 4];
__device__ int    g_rowptr[NN + 1];
__device__ int    g_cnt[NN];
__device__ int    g_perm[ETOT];

__device__ __forceinline__ int edge_src(const int* ei, int e) {
    return (e < EIN) ? ei[e] : (e - EIN);
}
__device__ __forceinline__ int edge_dst(const int* ei, int e) {
    return (e < EIN) ? ei[EIN + e] : (e - EIN);
}

// ---------------- fp32 -> fp16 convert ----------------
__global__ void f2h(const float* __restrict__ in, __half* __restrict__ out, int n4) {
    int i = blockIdx.x * blockDim.x + threadIdx.x;
    if (i < n4) {
        float4 v = *(const float4*)&in[i * 4];
        __half2 lo = __floats2half2_rn(v.x, v.y);
        __half2 hi = __floats2half2_rn(v.z, v.w);
        *(__half2*)&out[i * 4]     = lo;
        *(__half2*)&out[i * 4 + 2] = hi;
    }
}

// ---------------- CSR build ----------------
__global__ void k_zero_cnt() {
    int i = blockIdx.x * blockDim.x + threadIdx.x;
    if (i < NN) g_cnt[i] = 0;
}

__global__ void k_count(const int* __restrict__ ei) {
    int e = blockIdx.x * blockDim.x + threadIdx.x;
    if (e < ETOT) atomicAdd(&g_cnt[edge_dst(ei, e)], 1);
}

__global__ void k_scan() {
    __shared__ int warp_sums[32];
    __shared__ int carry_sh;
    int t = threadIdx.x, lane = t & 31, w = t >> 5;
    if (t == 0) { carry_sh = 0; g_rowptr[0] = 0; }
    __syncthreads();
    for (int base = 0; base < NN; base += 1024) {
        int v = (base + t < NN) ? g_cnt[base + t] : 0;
        int s = v;
#pragma unroll
        for (int off = 1; off < 32; off <<= 1) {
            int x = __shfl_up_sync(0xffffffffu, s, off);
            if (lane >= off) s += x;
        }
        if (lane == 31) warp_sums[w] = s;
        __syncthreads();
        if (w == 0) {
            int ws = warp_sums[lane];
#pragma unroll
            for (int off = 1; off < 32; off <<= 1) {
                int x = __shfl_up_sync(0xffffffffu, ws, off);
                if (lane >= off) ws += x;
            }
            warp_sums[lane] = ws;
        }
        __syncthreads();
        int incl = s + ((w > 0) ? warp_sums[w - 1] : 0) + carry_sh;
        if (base + t < NN) g_rowptr[base + t + 1] = incl;
        __syncthreads();
        if (t == 1023) carry_sh = incl;
        __syncthreads();
    }
}

__global__ void k_scatter(const int* __restrict__ ei) {
    int e = blockIdx.x * blockDim.x + threadIdx.x;
    if (e < ETOT) {
        int d = edge_dst(ei, e);
        int p = atomicAdd(&g_cnt[d], 1);
        g_perm[g_rowptr[d] + p] = e;
    }
}

// ---------------- FP16 GEMM: cp.async double-buffered, ldmatrix(.trans) ----------------
// C[M,N] = A[M,K]*B[K,N], all fp16 (fp32 accum). 128x128 block, K-tile 32, 8 warps.
#define CP16(smem_u32, gptr) \
    asm volatile("cp.async.cg.shared.global [%0], [%1], 16;" :: "r"(smem_u32), "l"(gptr))
#define CP_COMMIT() asm volatile("cp.async.commit_group;")

__global__ __launch_bounds__(256) void gemm_f16(
    const __half* __restrict__ A, const __half* __restrict__ B,
    __half* __restrict__ C, int M, int N, int K)
{
    __shared__ __align__(16) __half As[2][128][40];
    __shared__ __align__(16) __half Bs[2][32][136];

    const int tid  = threadIdx.x;
    const int warp = tid >> 5, lane = tid & 31;
    const int warpM = warp >> 2, warpN = warp & 3;
    const int bm = blockIdx.y * 128, bn = blockIdx.x * 128;
    const int gid = lane >> 2, tig = lane & 3;

    float c[4][4][4];
#pragma unroll
    for (int mt = 0; mt < 4; mt++)
#pragma unroll
        for (int nt = 0; nt < 4; nt++)
#pragma unroll
            for (int r = 0; r < 4; r++) c[mt][nt][r] = 0.f;

    const int ntiles = K >> 5;

    // per-thread load assignments: 2 chunks of 8 halves (16B) for A and B each
    const int ach0 = tid * 2, ach1 = tid * 2 + 1;

#define ISSUE_TILE(stage, k0)                                                     \
    {                                                                             \
        int _ar0 = ach0 >> 2, _ac0 = (ach0 & 3) * 8;                              \
        int _ar1 = ach1 >> 2, _ac1 = (ach1 & 3) * 8;                              \
        if (bm + _ar0 < M) {                                                      \
            unsigned _s = (unsigned)__cvta_generic_to_shared(&As[stage][_ar0][_ac0]); \
            CP16(_s, &A[(size_t)(bm + _ar0) * K + (k0) + _ac0]);                  \
        }                                                                         \
        if (bm + _ar1 < M) {                                                      \
            unsigned _s = (unsigned)__cvta_generic_to_shared(&As[stage][_ar1][_ac1]); \
            CP16(_s, &A[(size_t)(bm + _ar1) * K + (k0) + _ac1]);                  \
        }                                                                         \
        int _br0 = ach0 >> 4, _bc0 = (ach0 & 15) * 8;                             \
        int _br1 = ach1 >> 4, _bc1 = (ach1 & 15) * 8;                             \
        {                                                                         \
            unsigned _s = (unsigned)__cvta_generic_to_shared(&Bs[stage][_br0][_bc0]); \
            CP16(_s, &B[(size_t)((k0) + _br0) * N + bn + _bc0]);                  \
            _s = (unsigned)__cvta_generic_to_shared(&Bs[stage][_br1][_bc1]);      \
            CP16(_s, &B[(size_t)((k0) + _br1) * N + bn + _bc1]);                  \
        }                                                                         \
        CP_COMMIT();                                                              \
    }

    ISSUE_TILE(0, 0);
    if (ntiles > 1) ISSUE_TILE(1, 32);

    for (int kt = 0; kt < ntiles; kt++) {
        if (kt + 1 < ntiles)
            asm volatile("cp.async.wait_group 1;");
        else
            asm volatile("cp.async.wait_group 0;");
        __syncthreads();

        const int s = kt & 1;
#pragma unroll
        for (int ks = 0; ks < 2; ks++) {
            const int kb = ks * 16;
            unsigned a[4][4], b[4][2];
#pragma unroll
            for (int mt = 0; mt < 4; mt++) {
                int m  = warpM * 64 + mt * 16 + (lane & 15);
                int kc = kb + 8 * (lane >> 4);
                unsigned addr = (unsigned)__cvta_generic_to_shared(&As[s][m][kc]);
                asm volatile(
                    "ldmatrix.sync.aligned.m8n8.x4.shared.b16 {%0,%1,%2,%3}, [%4];"
                    : "=r"(a[mt][0]), "=r"(a[mt][1]), "=r"(a[mt][2]), "=r"(a[mt][3])
                    : "r"(addr));
            }
#pragma unroll
            for (int np = 0; np < 2; np++) {
                int kr = kb + (lane & 15);
                int nc = warpN * 32 + np * 16 + 8 * (lane >> 4);
                unsigned addr = (unsigned)__cvta_generic_to_shared(&Bs[s][kr][nc]);
                unsigned r0, r1, r2, r3;
                asm volatile(
                    "ldmatrix.sync.aligned.m8n8.x4.trans.shared.b16 {%0,%1,%2,%3}, [%4];"
                    : "=r"(r0), "=r"(r1), "=r"(r2), "=r"(r3)
                    : "r"(addr));
                b[np * 2][0]     = r0;
                b[np * 2][1]     = r1;
                b[np * 2 + 1][0] = r2;
                b[np * 2 + 1][1] = r3;
            }
#pragma unroll
            for (int mt = 0; mt < 4; mt++)
#pragma unroll
                for (int nt = 0; nt < 4; nt++) {
                    asm volatile(
                        "mma.sync.aligned.m16n8k16.row.col.f32.f16.f16.f32 "
                        "{%0,%1,%2,%3}, {%4,%5,%6,%7}, {%8,%9}, {%0,%1,%2,%3};"
                        : "+f"(c[mt][nt][0]), "+f"(c[mt][nt][1]),
                          "+f"(c[mt][nt][2]), "+f"(c[mt][nt][3])
                        : "r"(a[mt][0]), "r"(a[mt][1]), "r"(a[mt][2]), "r"(a[mt][3]),
                          "r"(b[nt][0]), "r"(b[nt][1]));
                }
        }
        __syncthreads();
        if (kt + 2 < ntiles) ISSUE_TILE(kt & 1, (kt + 2) * 32);
    }

    // fp16 epilogue
#pragma unroll
    for (int mt = 0; mt < 4; mt++) {
        int row0 = bm + warpM * 64 + mt * 16 + gid;
#pragma unroll
        for (int nt = 0; nt < 4; nt++) {
            int col = bn + warpN * 32 + nt * 8 + tig * 2;
            if (col < N) {
                if (row0 < M)
                    *(__half2*)&C[(size_t)row0 * N + col] =
                        __floats2half2_rn(c[mt][nt][0], c[mt][nt][1]);
                if (row0 + 8 < M)
                    *(__half2*)&C[(size_t)(row0 + 8) * N + col] =
                        __floats2half2_rn(c[mt][nt][2], c[mt][nt][3]);
            }
        }
    }
}

// ---------------- per-node attention logits (fp16 feat) ----------------
__global__ void node_al(const __half* __restrict__ feat,
                        const float* __restrict__ a_src,
                        const float* __restrict__ a_dst,
                        int Hn, int Cn)
{
    int n = blockIdx.x;
    int w = threadIdx.x >> 5;
    int lane = threadIdx.x & 31;
    if (w >= Hn) return;
    const __half* row = feat + (size_t)n * Hn * Cn + w * Cn;
    float s1 = 0.f, s2 = 0.f;
    for (int c = lane; c < Cn; c += 32) {
        float v = __half2float(row[c]);
        s1 += v * a_src[w * Cn + c];
        s2 += v * a_dst[w * Cn + c];
    }
#pragma unroll
    for (int off = 16; off; off >>= 1) {
        s1 += __shfl_xor_sync(0xffffffffu, s1, off);
        s2 += __shfl_xor_sync(0xffffffffu, s2, off);
    }
    if (lane == 0) {
        g_als[n * Hn + w] = s1;
        g_ald[n * Hn + w] = s2;
    }
}

// ---------------- edge logits ----------------
__global__ void k_edge(const int* __restrict__ ei, int Hn) {
    int idx = blockIdx.x * blockDim.x + threadIdx.x;
    if (idx >= ETOT * Hn) return;
    int e = idx / Hn;
    int hh = idx - e * Hn;
    int s = edge_src(ei, e);
    int d = edge_dst(ei, e);
    float v = g_als[s * Hn + hh] + g_ald[d * Hn + hh];
    g_e[idx] = (v > 0.f) ? v : 0.2f * v;
}

// ---------------- per-dst softmax + aggregation (fp16 feat) ----------------
template <int H, int C, bool F16OUT>
__global__ void gat_agg(const __half* __restrict__ feat,
                        const int* __restrict__ ei,
                        const float* __restrict__ bias,
                        float* __restrict__ outf,
                        __half* __restrict__ outh,
                        int apply_elu)
{
    constexpr int HCv = H * C;
    constexpr int CHUNK = 128;
    int n = blockIdx.x;
    int t = threadIdx.x;

    int start = g_rowptr[n];
    int deg = g_rowptr[n + 1] - start;

    __shared__ float m_sh[H];
    __shared__ float d_sh[H];
    __shared__ float alpha_sh[CHUNK * H];
    __shared__ int   src_sh[CHUNK];
    __shared__ int   eid_sh[CHUNK];

    int warp = t >> 5, lane = t & 31;
    if (warp < H) {
        float mx = -1e30f;
        for (int j = lane; j < deg; j += 32)
            mx = fmaxf(mx, g_e[g_perm[start + j] * H + warp]);
#pragma unroll
        for (int off = 16; off; off >>= 1)
            mx = fmaxf(mx, __shfl_xor_sync(0xffffffffu, mx, off));
        float s = 0.f;
        for (int j = lane; j < deg; j += 32)
            s += __expf(g_e[g_perm[start + j] * H + warp] - mx);
#pragma unroll
        for (int off = 16; off; off >>= 1)
            s += __shfl_xor_sync(0xffffffffu, s, off);
        if (lane == 0) { m_sh[warp] = mx; d_sh[warp] = s; }
    }
    __syncthreads();

    const int head = t / C;
    float acc = 0.f;

    for (int cs = 0; cs < deg; cs += CHUNK) {
        int cn = min(CHUNK, deg - cs);
        for (int i = t; i < cn; i += HCv) {
            int eidx = g_perm[start + cs + i];
            eid_sh[i] = eidx;
            src_sh[i] = edge_src(ei, eidx);
        }
        __syncthreads();
        for (int i = t; i < cn * H; i += HCv) {
            int j = i / H, hh = i - j * H;
            alpha_sh[i] = __expf(g_e[eid_sh[j] * H + hh] - m_sh[hh]) / d_sh[hh];
        }
        __syncthreads();
#pragma unroll 4
        for (int j = 0; j < cn; j++) {
            acc += alpha_sh[j * H + head] *
                   __half2float(feat[(size_t)src_sh[j] * HCv + t]);
        }
        __syncthreads();
    }

    float v = acc + bias[t];
    if (apply_elu) v = (v > 0.f) ? v : (__expf(v) - 1.f);
    if (F16OUT)
        outh[(size_t)n * HCv + t] = __float2half_rn(v);
    else
        outf[(size_t)n * HCv + t] = v;
}

// ---------------- launch ----------------
extern "C" void kernel_launch(void* const* d_in, const int* in_sizes, int n_in,
                              void* d_out, int out_size)
{
    const float* x   = (const float*)d_in[0];
    const int*   ei  = (const int*)d_in[1];
    const float* W1  = (const float*)d_in[2];
    const float* as1 = (const float*)d_in[3];
    const float* ad1 = (const float*)d_in[4];
    const float* b1  = (const float*)d_in[5];
    const float* W2  = (const float*)d_in[6];
    const float* as2 = (const float*)d_in[7];
    const float* ad2 = (const float*)d_in[8];
    const float* b2  = (const float*)d_in[9];
    const float* W3  = (const float*)d_in[10];
    const float* as3 = (const float*)d_in[11];
    const float* ad3 = (const float*)d_in[12];
    const float* b3  = (const float*)d_in[13];
    float* out = (float*)d_out;

    __half *x16, *w1, *w2, *w3, *h16, *o16;
    cudaGetSymbolAddress((void**)&x16, g_x16);
    cudaGetSymbolAddress((void**)&w1, g_w1);
    cudaGetSymbolAddress((void**)&w2, g_w2);
    cudaGetSymbolAddress((void**)&w3, g_w3);
    cudaGetSymbolAddress((void**)&h16, g_h16);
    cudaGetSymbolAddress((void**)&o16, g_o16);

    // --- fp16 conversions ---
    f2h<<<(NN * 256 / 4 + 255) / 256, 256>>>(x, x16, NN * 256 / 4);
    f2h<<<(256 * 512 / 4 + 255) / 256, 256>>>(W1, w1, 256 * 512 / 4);
    f2h<<<(512 * 512 / 4 + 255) / 256, 256>>>(W2, w2, 512 * 512 / 4);
    f2h<<<(512 * 64 / 4 + 255) / 256, 256>>>(W3, w3, 512 * 64 / 4);

    // --- CSR build ---
    k_zero_cnt<<<(NN + 255) / 256, 256>>>();
    k_count<<<(ETOT + 255) / 256, 256>>>(ei);
    k_scan<<<1, 1024>>>();
    k_zero_cnt<<<(NN + 255) / 256, 256>>>();
    k_scatter<<<(ETOT + 255) / 256, 256>>>(ei);

    dim3 g1((512 + 127) / 128, (NN + 127) / 128);
    dim3 g3(1, (NN + 127) / 128);

    // --- layer 1 ---
    gemm_f16<<<g1, 256>>>(x16, w1, h16, NN, 512, 256);
    node_al<<<NN, 128>>>(h16, as1, ad1, 4, 128);
    k_edge<<<(ETOT * 4 + 255) / 256, 256>>>(ei, 4);
    gat_agg<4, 128, true><<<NN, 512>>>(h16, ei, b1, nullptr, o16, 1);

    // --- layer 2 ---
    gemm_f16<<<g1, 256>>>(o16, w2, h16, NN, 512, 512);
    node_al<<<NN, 128>>>(h16, as2, ad2, 4, 128);
    k_edge<<<(ETOT * 4 + 255) / 256, 256>>>(ei, 4);
    gat_agg<4, 128, true><<<NN, 512>>>(h16, ei, b2, nullptr, o16, 1);

    // --- layer 3 ---
    gemm_f16<<<g3, 256>>>(o16, w3, h16, NN, 64, 512);
    node_al<<<NN, 32>>>(h16, as3, ad3, 1, 64);
    k_edge<<<(ETOT + 255) / 256, 256>>>(ei, 1);
    gat_agg<1, 64, false><<<NN, 64>>>(h16, ei, b3, out, nullptr, 0);
}

// round 7
// speedup vs baseline: 2.6208x; 1.4023x over previous
#include <cuda_runtime.h>
#include <cuda_fp16.h>
#include <math.h>

#define NN   10000
#define EIN  320000
#define ETOT 330000
#define MAXD 1024

// ---------------- device scratch ----------------
__device__ __half g_x16[NN * 256];
__device__ __half g_w1[256 * 512];
__device__ __half g_w2[512 * 512];
__device__ __half g_w3[512 * 64 + 256];   // pad for OOB-column reads in 128-wide tile
__device__ __half g_h16[NN * 512];
__device__ __half g_o16[NN * 512];
__device__ float  g_als[NN * 4];
__device__ float  g_ald[NN * 4];
__device__ int    g_rowptr[NN + 1];
__device__ int    g_cnt[NN];
__device__ int    g_srcs[ETOT];           // src node per edge, dst-sorted order

__device__ __forceinline__ int edge_src(const int* ei, int e) {
    return (e < EIN) ? ei[e] : (e - EIN);
}
__device__ __forceinline__ int edge_dst(const int* ei, int e) {
    return (e < EIN) ? ei[EIN + e] : (e - EIN);
}

// ---------------- fp32 -> fp16 convert ----------------
__global__ void f2h(const float* __restrict__ in, __half* __restrict__ out, int n4) {
    int i = blockIdx.x * blockDim.x + threadIdx.x;
    if (i < n4) {
        float4 v = *(const float4*)&in[i * 4];
        *(__half2*)&out[i * 4]     = __floats2half2_rn(v.x, v.y);
        *(__half2*)&out[i * 4 + 2] = __floats2half2_rn(v.z, v.w);
    }
}

// ---------------- CSR build ----------------
__global__ void k_zero_cnt() {
    int i = blockIdx.x * blockDim.x + threadIdx.x;
    if (i < NN) g_cnt[i] = 0;
}

__global__ void k_count(const int* __restrict__ ei) {
    int e = blockIdx.x * blockDim.x + threadIdx.x;
    if (e < ETOT) atomicAdd(&g_cnt[edge_dst(ei, e)], 1);
}

__global__ void k_scan() {
    __shared__ int warp_sums[32];
    __shared__ int carry_sh;
    int t = threadIdx.x, lane = t & 31, w = t >> 5;
    if (t == 0) { carry_sh = 0; g_rowptr[0] = 0; }
    __syncthreads();
    for (int base = 0; base < NN; base += 1024) {
        int v = (base + t < NN) ? g_cnt[base + t] : 0;
        int s = v;
#pragma unroll
        for (int off = 1; off < 32; off <<= 1) {
            int x = __shfl_up_sync(0xffffffffu, s, off);
            if (lane >= off) s += x;
        }
        if (lane == 31) warp_sums[w] = s;
        __syncthreads();
        if (w == 0) {
            int ws = warp_sums[lane];
#pragma unroll
            for (int off = 1; off < 32; off <<= 1) {
                int x = __shfl_up_sync(0xffffffffu, ws, off);
                if (lane >= off) ws += x;
            }
            warp_sums[lane] = ws;
        }
        __syncthreads();
        int incl = s + ((w > 0) ? warp_sums[w - 1] : 0) + carry_sh;
        if (base + t < NN) g_rowptr[base + t + 1] = incl;
        __syncthreads();
        if (t == 1023) carry_sh = incl;
        __syncthreads();
    }
}

__global__ void k_scatter(const int* __restrict__ ei) {
    int e = blockIdx.x * blockDim.x + threadIdx.x;
    if (e < ETOT) {
        int d = edge_dst(ei, e);
        int p = atomicAdd(&g_cnt[d], 1);
        g_srcs[g_rowptr[d] + p] = edge_src(ei, e);
    }
}

// ---------------- FP16 GEMM: cp.async double-buffered, ldmatrix(.trans) ----------------
#define CP16(smem_u32, gptr) \
    asm volatile("cp.async.cg.shared.global [%0], [%1], 16;" :: "r"(smem_u32), "l"(gptr))
#define CP_COMMIT() asm volatile("cp.async.commit_group;")

__global__ __launch_bounds__(256) void gemm_f16(
    const __half* __restrict__ A, const __half* __restrict__ B,
    __half* __restrict__ C, int M, int N, int K)
{
    __shared__ __align__(16) __half As[2][128][40];
    __shared__ __align__(16) __half Bs[2][32][136];

    const int tid  = threadIdx.x;
    const int warp = tid >> 5, lane = tid & 31;
    const int warpM = warp >> 2, warpN = warp & 3;
    const int bm = blockIdx.y * 128, bn = blockIdx.x * 128;
    const int gid = lane >> 2, tig = lane & 3;

    float c[4][4][4];
#pragma unroll
    for (int mt = 0; mt < 4; mt++)
#pragma unroll
        for (int nt = 0; nt < 4; nt++)
#pragma unroll
            for (int r = 0; r < 4; r++) c[mt][nt][r] = 0.f;

    const int ntiles = K >> 5;
    const int ach0 = tid * 2, ach1 = tid * 2 + 1;

#define ISSUE_TILE(stage, k0)                                                     \
    {                                                                             \
        int _ar0 = ach0 >> 2, _ac0 = (ach0 & 3) * 8;                              \
        int _ar1 = ach1 >> 2, _ac1 = (ach1 & 3) * 8;                              \
        if (bm + _ar0 < M) {                                                      \
            unsigned _s = (unsigned)__cvta_generic_to_shared(&As[stage][_ar0][_ac0]); \
            CP16(_s, &A[(size_t)(bm + _ar0) * K + (k0) + _ac0]);                  \
        }                                                                         \
        if (bm + _ar1 < M) {                                                      \
            unsigned _s = (unsigned)__cvta_generic_to_shared(&As[stage][_ar1][_ac1]); \
            CP16(_s, &A[(size_t)(bm + _ar1) * K + (k0) + _ac1]);                  \
        }                                                                         \
        int _br0 = ach0 >> 4, _bc0 = (ach0 & 15) * 8;                             \
        int _br1 = ach1 >> 4, _bc1 = (ach1 & 15) * 8;                             \
        {                                                                         \
            unsigned _s = (unsigned)__cvta_generic_to_shared(&Bs[stage][_br0][_bc0]); \
            CP16(_s, &B[(size_t)((k0) + _br0) * N + bn + _bc0]);                  \
            _s = (unsigned)__cvta_generic_to_shared(&Bs[stage][_br1][_bc1]);      \
            CP16(_s, &B[(size_t)((k0) + _br1) * N + bn + _bc1]);                  \
        }                                                                         \
        CP_COMMIT();                                                              \
    }

    ISSUE_TILE(0, 0);
    if (ntiles > 1) ISSUE_TILE(1, 32);

    for (int kt = 0; kt < ntiles; kt++) {
        if (kt + 1 < ntiles)
            asm volatile("cp.async.wait_group 1;");
        else
            asm volatile("cp.async.wait_group 0;");
        __syncthreads();

        const int s = kt & 1;
#pragma unroll
        for (int ks = 0; ks < 2; ks++) {
            const int kb = ks * 16;
            unsigned a[4][4], b[4][2];
#pragma unroll
            for (int mt = 0; mt < 4; mt++) {
                int m  = warpM * 64 + mt * 16 + (lane & 15);
                int kc = kb + 8 * (lane >> 4);
                unsigned addr = (unsigned)__cvta_generic_to_shared(&As[s][m][kc]);
                asm volatile(
                    "ldmatrix.sync.aligned.m8n8.x4.shared.b16 {%0,%1,%2,%3}, [%4];"
                    : "=r"(a[mt][0]), "=r"(a[mt][1]), "=r"(a[mt][2]), "=r"(a[mt][3])
                    : "r"(addr));
            }
#pragma unroll
            for (int np = 0; np < 2; np++) {
                int kr = kb + (lane & 15);
                int nc = warpN * 32 + np * 16 + 8 * (lane >> 4);
                unsigned addr = (unsigned)__cvta_generic_to_shared(&Bs[s][kr][nc]);
                unsigned r0, r1, r2, r3;
                asm volatile(
                    "ldmatrix.sync.aligned.m8n8.x4.trans.shared.b16 {%0,%1,%2,%3}, [%4];"
                    : "=r"(r0), "=r"(r1), "=r"(r2), "=r"(r3)
                    : "r"(addr));
                b[np * 2][0]     = r0;
                b[np * 2][1]     = r1;
                b[np * 2 + 1][0] = r2;
                b[np * 2 + 1][1] = r3;
            }
#pragma unroll
            for (int mt = 0; mt < 4; mt++)
#pragma unroll
                for (int nt = 0; nt < 4; nt++) {
                    asm volatile(
                        "mma.sync.aligned.m16n8k16.row.col.f32.f16.f16.f32 "
                        "{%0,%1,%2,%3}, {%4,%5,%6,%7}, {%8,%9}, {%0,%1,%2,%3};"
                        : "+f"(c[mt][nt][0]), "+f"(c[mt][nt][1]),
                          "+f"(c[mt][nt][2]), "+f"(c[mt][nt][3])
                        : "r"(a[mt][0]), "r"(a[mt][1]), "r"(a[mt][2]), "r"(a[mt][3]),
                          "r"(b[nt][0]), "r"(b[nt][1]));
                }
        }
        __syncthreads();
        if (kt + 2 < ntiles) ISSUE_TILE(kt & 1, (kt + 2) * 32);
    }

#pragma unroll
    for (int mt = 0; mt < 4; mt++) {
        int row0 = bm + warpM * 64 + mt * 16 + gid;
#pragma unroll
        for (int nt = 0; nt < 4; nt++) {
            int col = bn + warpN * 32 + nt * 8 + tig * 2;
            if (col < N) {
                if (row0 < M)
                    *(__half2*)&C[(size_t)row0 * N + col] =
                        __floats2half2_rn(c[mt][nt][0], c[mt][nt][1]);
                if (row0 + 8 < M)
                    *(__half2*)&C[(size_t)(row0 + 8) * N + col] =
                        __floats2half2_rn(c[mt][nt][2], c[mt][nt][3]);
            }
        }
    }
}

// ---------------- per-node attention logits (fp16 feat) ----------------
__global__ void node_al(const __half* __restrict__ feat,
                        const float* __restrict__ a_src,
                        const float* __restrict__ a_dst,
                        int Hn, int Cn)
{
    int n = blockIdx.x;
    int w = threadIdx.x >> 5;
    int lane = threadIdx.x & 31;
    if (w >= Hn) return;
    const __half* row = feat + (size_t)n * Hn * Cn + w * Cn;
    float s1 = 0.f, s2 = 0.f;
    for (int c = lane; c < Cn; c += 32) {
        float v = __half2float(row[c]);
        s1 += v * a_src[w * Cn + c];
        s2 += v * a_dst[w * Cn + c];
    }
#pragma unroll
    for (int off = 16; off; off >>= 1) {
        s1 += __shfl_xor_sync(0xffffffffu, s1, off);
        s2 += __shfl_xor_sync(0xffffffffu, s2, off);
    }
    if (lane == 0) {
        g_als[n * Hn + w] = s1;
        g_ald[n * Hn + w] = s2;
    }
}

// ---------------- fused softmax + aggregation ----------------
// block = H*C/2 threads, each thread handles 2 channels via half2.
// Edge logits computed on the fly from g_als/g_ald, cached in smem.
// Windowed online softmax (exact); window MAXD >= max degree in practice.
template <int H, int C, bool F16OUT>
__global__ void gat_agg(const __half* __restrict__ feat,
                        const float* __restrict__ bias,
                        float* __restrict__ outf,
                        __half* __restrict__ outh,
                        int apply_elu)
{
    constexpr int HCv = H * C;
    constexpr int BT = HCv / 2;
    int n = blockIdx.x;
    int t = threadIdx.x;
    int warp = t >> 5, lane = t & 31;

    int start = g_rowptr[n];
    int deg = g_rowptr[n + 1] - start;

    __shared__ float e_sh[MAXD * H];
    __shared__ int   src_sh[MAXD];
    __shared__ float m_run[H], d_run[H], f_sh[H];

    if (t < H) { m_run[t] = -1e30f; d_run[t] = 0.f; }

    // dst-side logits (broadcast per block)
    float aldv[H];
#pragma unroll
    for (int hh = 0; hh < H; hh++) aldv[hh] = g_ald[n * H + hh];

    const int hd = (2 * t) / C;   // head for this thread's channel pair
    float2 acc = make_float2(0.f, 0.f);
    const __half2* feat2 = (const __half2*)feat;

    for (int w0 = 0; w0 < deg; w0 += MAXD) {
        int wn = min(MAXD, deg - w0);
        __syncthreads();   // protect e_sh/src_sh reuse across windows

        // load pass: gather src logits, compute leaky-relu logits into smem
        for (int i = t; i < wn; i += BT) {
            int s = g_srcs[start + w0 + i];
            src_sh[i] = s;
            if (H == 4) {
                float4 av = *(const float4*)&g_als[s * 4];
                float e0 = av.x + aldv[0], e1 = av.y + aldv[1];
                float e2 = av.z + aldv[2], e3 = av.w + aldv[3];
                e_sh[i * 4 + 0] = (e0 > 0.f) ? e0 : 0.2f * e0;
                e_sh[i * 4 + 1] = (e1 > 0.f) ? e1 : 0.2f * e1;
                e_sh[i * 4 + 2] = (e2 > 0.f) ? e2 : 0.2f * e2;
                e_sh[i * 4 + 3] = (e3 > 0.f) ? e3 : 0.2f * e3;
            } else {
                float e0 = g_als[s] + aldv[0];
                e_sh[i] = (e0 > 0.f) ? e0 : 0.2f * e0;
            }
        }
        __syncthreads();

        // per-head online max/sum update
        if (warp < H) {
            float wm = -1e30f;
            for (int j = lane; j < wn; j += 32)
                wm = fmaxf(wm, e_sh[j * H + warp]);
#pragma unroll
            for (int off = 16; off; off >>= 1)
                wm = fmaxf(wm, __shfl_xor_sync(0xffffffffu, wm, off));
            float nm = fmaxf(m_run[warp], wm);
            float s = 0.f;
            for (int j = lane; j < wn; j += 32)
                s += __expf(e_sh[j * H + warp] - nm);
#pragma unroll
            for (int off = 16; off; off >>= 1)
                s += __shfl_xor_sync(0xffffffffu, s, off);
            if (lane == 0) {
                float f = __expf(m_run[warp] - nm);
                f_sh[warp] = f;
                d_run[warp] = d_run[warp] * f + s;
                m_run[warp] = nm;
            }
        }
        __syncthreads();

        // exponentiate logits in place
        for (int i = t; i < wn * H; i += BT) {
            int hh = i & (H - 1);
            e_sh[i] = __expf(e_sh[i] - m_run[hh]);
        }
        acc.x *= f_sh[hd];
        acc.y *= f_sh[hd];
        __syncthreads();

        // weighted feature accumulation
        int j = 0;
        for (; j + 4 <= wn; j += 4) {
#pragma unroll
            for (int u = 0; u < 4; u++) {
                float w = e_sh[(j + u) * H + hd];
                float2 f = __half22float2(feat2[(size_t)src_sh[j + u] * (HCv / 2) + t]);
                acc.x += w * f.x;
                acc.y += w * f.y;
            }
        }
        for (; j < wn; j++) {
            float w = e_sh[j * H + hd];
            float2 f = __half22float2(feat2[(size_t)src_sh[j] * (HCv / 2) + t]);
            acc.x += w * f.x;
            acc.y += w * f.y;
        }
    }

    float inv = 1.f / d_run[hd];
    float v0 = acc.x * inv + bias[2 * t];
    float v1 = acc.y * inv + bias[2 * t + 1];
    if (apply_elu) {
        v0 = (v0 > 0.f) ? v0 : (__expf(v0) - 1.f);
        v1 = (v1 > 0.f) ? v1 : (__expf(v1) - 1.f);
    }
    if (F16OUT)
        *(__half2*)&outh[(size_t)n * HCv + 2 * t] = __floats2half2_rn(v0, v1);
    else
        *(float2*)&outf[(size_t)n * HCv + 2 * t] = make_float2(v0, v1);
}

// ---------------- launch ----------------
extern "C" void kernel_launch(void* const* d_in, const int* in_sizes, int n_in,
                              void* d_out, int out_size)
{
    const float* x   = (const float*)d_in[0];
    const int*   ei  = (const int*)d_in[1];
    const float* W1  = (const float*)d_in[2];
    const float* as1 = (const float*)d_in[3];
    const float* ad1 = (const float*)d_in[4];
    const float* b1  = (const float*)d_in[5];
    const float* W2  = (const float*)d_in[6];
    const float* as2 = (const float*)d_in[7];
    const float* ad2 = (const float*)d_in[8];
    const float* b2  = (const float*)d_in[9];
    const float* W3  = (const float*)d_in[10];
    const float* as3 = (const float*)d_in[11];
    const float* ad3 = (const float*)d_in[12];
    const float* b3  = (const float*)d_in[13];
    float* out = (float*)d_out;

    __half *x16, *w1, *w2, *w3, *h16, *o16;
    cudaGetSymbolAddress((void**)&x16, g_x16);
    cudaGetSymbolAddress((void**)&w1, g_w1);
    cudaGetSymbolAddress((void**)&w2, g_w2);
    cudaGetSymbolAddress((void**)&w3, g_w3);
    cudaGetSymbolAddress((void**)&h16, g_h16);
    cudaGetSymbolAddress((void**)&o16, g_o16);

    // --- fp16 conversions ---
    f2h<<<(NN * 256 / 4 + 255) / 256, 256>>>(x, x16, NN * 256 / 4);
    f2h<<<(256 * 512 / 4 + 255) / 256, 256>>>(W1, w1, 256 * 512 / 4);
    f2h<<<(512 * 512 / 4 + 255) / 256, 256>>>(W2, w2, 512 * 512 / 4);
    f2h<<<(512 * 64 / 4 + 255) / 256, 256>>>(W3, w3, 512 * 64 / 4);

    // --- CSR build ---
    k_zero_cnt<<<(NN + 255) / 256, 256>>>();
    k_count<<<(ETOT + 255) / 256, 256>>>(ei);
    k_scan<<<1, 1024>>>();
    k_zero_cnt<<<(NN + 255) / 256, 256>>>();
    k_scatter<<<(ETOT + 255) / 256, 256>>>(ei);

    dim3 g1((512 + 127) / 128, (NN + 127) / 128);
    dim3 g3(1, (NN + 127) / 128);

    // --- layer 1 ---
    gemm_f16<<<g1, 256>>>(x16, w1, h16, NN, 512, 256);
    node_al<<<NN, 128>>>(h16, as1, ad1, 4, 128);
    gat_agg<4, 128, true><<<NN, 256>>>(h16, b1, nullptr, o16, 1);

    // --- layer 2 ---
    gemm_f16<<<g1, 256>>>(o16, w2, h16, NN, 512, 512);
    node_al<<<NN, 128>>>(h16, as2, ad2, 4, 128);
    gat_agg<4, 128, true><<<NN, 256>>>(h16, b2, nullptr, o16, 1);

    // --- layer 3 ---
    gemm_f16<<<g3, 256>>>(o16, w3, h16, NN, 64, 512);
    node_al<<<NN, 32>>>(h16, as3, ad3, 1, 64);
    gat_agg<1, 64, false><<<NN, 32>>>(h16, b3, out, nullptr, 0);
}